// round 15
// baseline (speedup 1.0000x reference)
#include <cuda_runtime.h>

// Problem constants
#define MAXN 100000
#define MAXE 1600000
#define MAXNT 784          // max node tiles of 128
#define FEAT 64
#define DN 128             // nodes per dense block / tile
#define SCAN_CHUNK 2048
#define MAXBLK 64

typedef unsigned long long ull;

// Scratch (__device__ globals; allocation-free rule). Referenced ONLY from
// device code — never passed as kernel args from host.
__device__ __align__(16) float g_h1  [MAXN * FEAT];       // layer-0 out, [n][k]
__device__ __align__(16) float g_xT  [MAXNT * 64 * 128];  // x transposed tiles
__device__ __align__(16) float g_h1T [MAXNT * 64 * 128];  // h1 transposed tiles
__device__ __align__(16) float g_aggT[MAXNT * 64 * 128];  // agg transposed tiles
__device__ __align__(16) float g_wT  [6 * 64 * 64];       // wl0,wr0,ws0,wl1,wr1,ws1 [k][d]
__device__ int g_cnt[MAXN];
__device__ int g_off[MAXN + 1];
__device__ int g_cur[MAXN];
__device__ int g_csr_src[MAXE];
__device__ int g_bsum[MAXBLK];
__device__ int g_bar;

// ---- packed f32x2 helpers (Blackwell PTX) ----------------------------------
__device__ __forceinline__ void fma2(ull& acc, ull av, ull wv)
{
    asm("fma.rn.f32x2 %0, %1, %2, %0;" : "+l"(acc) : "l"(av), "l"(wv));
}
__device__ __forceinline__ ull dup2(float w)
{
    ull r; asm("mov.b64 %0, {%1, %1};" : "=l"(r) : "f"(w)); return r;
}
__device__ __forceinline__ void unpk(float& lo, float& hi, ull v)
{
    asm("mov.b64 {%0, %1}, %2;" : "=f"(lo), "=f"(hi) : "l"(v));
}
__device__ __forceinline__ ull pk2(float lo, float hi)
{
    ull r; asm("mov.b64 %0, {%1, %2};" : "=l"(r) : "f"(lo), "f"(hi)); return r;
}

// ---- cp.async helpers -------------------------------------------------------
__device__ __forceinline__ void cp16(void* dst_smem, const void* src_gmem)
{
    unsigned u = (unsigned)__cvta_generic_to_shared(dst_smem);
    asm volatile("cp.async.cg.shared.global [%0], [%1], 16;"
                 :: "r"(u), "l"(src_gmem) : "memory");
}
#define CP_COMMIT() asm volatile("cp.async.commit_group;" ::: "memory")
#define CP_WAIT(n)  asm volatile("cp.async.wait_group %0;" :: "n"(n) : "memory")

// ---------------------------------------------------------------------------
// Smem-free tile transpose: feat [n][64] -> dT tile [k][128].
// Reads 16B chunks 256B apart (L2-resident); writes fully coalesced rows.
// ---------------------------------------------------------------------------
__device__ __forceinline__ void tile_transpose(const float* __restrict__ feat,
                                               float* __restrict__ dT,
                                               int t, int N)
{
    float* dst = dT + (size_t)t * 8192;
    for (int i = threadIdx.x; i < 2048; i += 256) {
        int n = i & 127, kq = i >> 7;        // kq in [0,16)
        int gn = t * DN + n;
        float4 v = make_float4(0.f, 0.f, 0.f, 0.f);
        if (gn < N) v = *(const float4*)&feat[gn * FEAT + kq * 4];
        dst[(4 * kq + 0) * 128 + n] = v.x;
        dst[(4 * kq + 1) * 128 + n] = v.y;
        dst[(4 * kq + 2) * 128 + n] = v.z;
        dst[(4 * kq + 3) * 128 + n] = v.w;
    }
}

// Software grid barrier over the first nb blocks (co-resident).
__device__ __forceinline__ void grid_bar(int target)
{
    __syncthreads();
    if (threadIdx.x == 0) {
        __threadfence();
        atomicAdd(&g_bar, 1);
        while (atomicAdd(&g_bar, 0) < target) { }
    }
    __syncthreads();
}

// ---------------------------------------------------------------------------
// Hist + scan + fill + transposes in ONE launch.
// Blocks [0,nb): phase A histogram (unroll-8 atomic chains) -> bar ->
//   exclusive scan (zeroes g_cnt -> invariant restore) -> bar -> offsets
//   (+g_off[N]=E) -> bar -> bucket edges (unroll-8 chains). Block 0 resets
//   g_bar at the end.
// Extra blocks [nb,nb+NT): x tile transposes -> g_xT (overlap the barriers).
// Extra blocks [nb+NT,nb+NT+6): weight transposes -> g_wT.
// ---------------------------------------------------------------------------
__global__ void scanfill_kernel(const int* __restrict__ src,
                                const int* __restrict__ dst,
                                int N, int E, int nb, int NT,
                                const float* __restrict__ x,
                                const float* __restrict__ w0, const float* __restrict__ w1,
                                const float* __restrict__ w2, const float* __restrict__ w3,
                                const float* __restrict__ w4, const float* __restrict__ w5)
{
    __shared__ int s_sum[256];
    int t = threadIdx.x;
    int b = blockIdx.x;

    if (b >= nb) {
        int tt = b - nb;
        if (tt < NT) {
            tile_transpose(x, g_xT, tt, N);
        } else {
            int m = tt - NT;      // weight transpose 0..5, writes coalesced in d
            if (m < 6) {
                const float* w = (m == 0) ? w0 : (m == 1) ? w1 : (m == 2) ? w2
                               : (m == 3) ? w3 : (m == 4) ? w4 : w5;
                for (int i = t; i < 4096; i += 256) {
                    int k = i >> 6, d = i & 63;
                    g_wT[m * 4096 + k * 64 + d] = w[d * 64 + k];
                }
            }
        }
        return;
    }

    int tg = b * blockDim.x + t;
    int T  = nb * blockDim.x;

    // phase A: histogram (g_cnt is 0 on entry; 8 atomic chains in flight)
    for (int eb = tg * 8; eb < E; eb += T * 8) {
#pragma unroll
        for (int j = 0; j < 8; j++) {
            int e = eb + j;
            if (e < E) atomicAdd(&g_cnt[dst[e]], 1);
        }
    }

    grid_bar(nb);

    // phase B: local exclusive scan; zero g_cnt as read (restores invariant)
    int base = b * SCAN_CHUNK + t * 8;
    int v[8], tot = 0;
#pragma unroll
    for (int j = 0; j < 8; j++) {
        int idx = base + j;
        if (idx < N) { v[j] = g_cnt[idx]; g_cnt[idx] = 0; }
        else v[j] = 0;
        tot += v[j];
    }
    s_sum[t] = tot;
    __syncthreads();
    for (int off = 1; off < 256; off <<= 1) {
        int xv = (t >= off) ? s_sum[t - off] : 0;
        __syncthreads();
        s_sum[t] += xv;
        __syncthreads();
    }
    if (t == 255) g_bsum[b] = s_sum[255];
    int run = s_sum[t] - tot;

    grid_bar(2 * nb);

    // phase C: global offsets
    int bpre = 0;
    for (int bb = 0; bb < b; bb++) bpre += g_bsum[bb];
    run += bpre;
#pragma unroll
    for (int j = 0; j < 8; j++) {
        int idx = base + j;
        if (idx < N) { g_off[idx] = run; g_cur[idx] = run; }
        run += v[j];
    }
    if (b == nb - 1 && t == 255) g_off[N] = E;

    grid_bar(3 * nb);

    // phase D: bucket edges by dst (8 atomic chains in flight)
    for (int eb = tg * 8; eb < E; eb += T * 8) {
#pragma unroll
        for (int j = 0; j < 8; j++) {
            int e = eb + j;
            if (e < E) {
                int p = atomicAdd(&g_cur[dst[e]], 1);
                g_csr_src[p] = src[e];
            }
        }
    }
    if (b == 0 && t == 0) g_bar = 0;   // restore invariant
}

// ---------------------------------------------------------------------------
// Aggregate (proven at ~95% L2 roofline): 8 warps/block = 8 nodes; lane
// covers feats (2l, 2l+1) as float2. Writes mean TRANSPOSED into g_aggT
// tiles via a small bank-safe smem bounce.
// ---------------------------------------------------------------------------
__global__ void agg_kernel(const float* __restrict__ x, int N, int layer)
{
    __shared__ float s[64 * 9];
    int b = blockIdx.x;
    int warp = threadIdx.x >> 5;
    int lane = threadIdx.x & 31;
    int node = b * 8 + warp;
    const float2* h2 = (const float2*)(layer ? g_h1 : x);

    float ax = 0.f, ay = 0.f;
    int deg = 0;
    if (node < N) {
        int start = g_off[node];
        deg = g_off[node + 1] - start;
        int i = 0;
        for (; i + 8 <= deg; i += 8) {
            int sidx[8];
#pragma unroll
            for (int j = 0; j < 8; j++) sidx[j] = g_csr_src[start + i + j];
            float2 v[8];
#pragma unroll
            for (int j = 0; j < 8; j++) v[j] = h2[sidx[j] * 32 + lane];
            ax += ((v[0].x + v[1].x) + (v[2].x + v[3].x))
                + ((v[4].x + v[5].x) + (v[6].x + v[7].x));
            ay += ((v[0].y + v[1].y) + (v[2].y + v[3].y))
                + ((v[4].y + v[5].y) + (v[6].y + v[7].y));
        }
        for (; i < deg; i++) {
            int sidx = g_csr_src[start + i];
            float2 v = h2[sidx * 32 + lane];
            ax += v.x; ay += v.y;
        }
    }
    float inv = 1.f / fmaxf((float)deg, 1.f);
    s[(2 * lane) * 9 + warp]     = ax * inv;
    s[(2 * lane + 1) * 9 + warp] = ay * inv;
    __syncthreads();

    int nbase = b * 8;
    int tile  = nbase >> 7;
    int nb2   = nbase & 127;
    float* dst = g_aggT + (size_t)tile * 8192;
    for (int i = threadIdx.x; i < 512; i += 256) {
        int k = i >> 3, n = i & 7;
        dst[k * 128 + nb2 + n] = s[k * 9 + n];
    }
}

// ---------------------------------------------------------------------------
// Dense phase (proven 57.8us): pre-transposed inputs -> pure cp.async staging,
// double-buffered (96KB, 2 blocks/SM). Thread tile 4d x 8n, f32x2 k-loop.
// Phases: agg@wl -> h@wr -> +bl,PReLU (regs) -> x@ws -> +bs.
// Layer 0 epilogue dual-writes h1 natural + h1T tiles (kills the separate
// h1 transpose pass).
// ---------------------------------------------------------------------------
__device__ __forceinline__ void dense_compute(const float* __restrict__ act,
                                              const float* __restrict__ w,
                                              ull acc[4][4], int d0, int n0)
{
#pragma unroll 4
    for (int k = 0; k < 64; k++) {
        float4 w4 = *(const float4*)&w[k * 64 + d0];
        ull wd[4];
        wd[0] = dup2(w4.x); wd[1] = dup2(w4.y);
        wd[2] = dup2(w4.z); wd[3] = dup2(w4.w);
        longlong2 p01 = *(const longlong2*)&act[k * 128 + n0];
        longlong2 p23 = *(const longlong2*)&act[k * 128 + n0 + 4];
        ull av[4];
        av[0] = (ull)p01.x; av[1] = (ull)p01.y;
        av[2] = (ull)p23.x; av[3] = (ull)p23.y;
#pragma unroll
        for (int dd = 0; dd < 4; dd++)
#pragma unroll
            for (int p = 0; p < 4; p++)
                fma2(acc[dd][p], av[p], wd[dd]);
    }
}

__global__ void __launch_bounds__(256, 2) dense_kernel(
    const float* __restrict__ x,
    const float* __restrict__ b_l, const float* __restrict__ b_skip,
    const float* __restrict__ a,
    float* __restrict__ out, int N, int layer)
{
    extern __shared__ __align__(16) float sm[];
    float* actA = sm;                  // [64][128]
    float* actB = sm + 8192;
    float* wA   = sm + 16384;          // [64][64]
    float* wB   = sm + 16384 + 4096;

    int tid  = threadIdx.x;
    int base = blockIdx.x * DN;
    int d0   = (tid & 15) * 4;
    int n0   = (tid >> 4) * 8;

    const float* aT = g_aggT + (size_t)blockIdx.x * 8192;
    const float* xT = g_xT   + (size_t)blockIdx.x * 8192;
    const float* hT = layer ? (g_h1T + (size_t)blockIdx.x * 8192) : xT;
    const float* wb = g_wT + layer * 3 * 4096;

    // prologue: stage p0 and p1
    for (int i = tid; i < 2048; i += 256) cp16(&actA[i * 4], &aT[i * 4]);
    for (int i = tid; i < 1024; i += 256) cp16(&wA[i * 4], &wb[i * 4]);
    CP_COMMIT();                                            // g1
    for (int i = tid; i < 2048; i += 256) cp16(&actB[i * 4], &hT[i * 4]);
    for (int i = tid; i < 1024; i += 256) cp16(&wB[i * 4], &wb[4096 + i * 4]);
    CP_COMMIT();                                            // g2

    float bl[4], bs[4], apar[4];
#pragma unroll
    for (int dd = 0; dd < 4; dd++) {
        bl[dd]   = b_l[d0 + dd];
        bs[dd]   = b_skip[d0 + dd];
        apar[dd] = a[d0 + dd];
    }

    ull acc[4][4];
#pragma unroll
    for (int dd = 0; dd < 4; dd++)
#pragma unroll
        for (int p = 0; p < 4; p++) acc[dd][p] = 0ULL;

    // ---- phase 0: agg @ wl ----
    CP_WAIT(1);
    __syncthreads();
    dense_compute(actA, wA, acc, d0, n0);
    __syncthreads();     // all reads of actA/wA done before g3 overwrites

    // stage p2 (layer0 reuses actB = x; layer1 restages actA with xT)
    if (layer) {
        for (int i = tid; i < 2048; i += 256) cp16(&actA[i * 4], &xT[i * 4]);
    }
    for (int i = tid; i < 1024; i += 256) cp16(&wA[i * 4], &wb[8192 + i * 4]);
    CP_COMMIT();                                            // g3

    // ---- phase 1: h @ wr ----
    CP_WAIT(1);
    __syncthreads();
    dense_compute(actB, wB, acc, d0, n0);

    // mid-epilogue in registers: acc = PReLU(acc + bl)
#pragma unroll
    for (int dd = 0; dd < 4; dd++)
#pragma unroll
        for (int p = 0; p < 4; p++) {
            float lo, hi;
            unpk(lo, hi, acc[dd][p]);
            lo += bl[dd]; hi += bl[dd];
            lo = (lo >= 0.f) ? lo : apar[dd] * lo;
            hi = (hi >= 0.f) ? hi : apar[dd] * hi;
            acc[dd][p] = pk2(lo, hi);
        }

    // ---- phase 2: x @ ws ----
    CP_WAIT(0);
    __syncthreads();
    dense_compute(layer ? actA : actB, wA, acc, d0, n0);

    // epilogue: out = acc + bs; layer0 also writes h1T tiles
    float* dstp = layer ? out : g_h1;
    float* hTo  = g_h1T + (size_t)blockIdx.x * 8192;
#pragma unroll
    for (int p = 0; p < 4; p++) {
        float lo[4], hi[4];
#pragma unroll
        for (int dd = 0; dd < 4; dd++) {
            unpk(lo[dd], hi[dd], acc[dd][p]);
            lo[dd] += bs[dd]; hi[dd] += bs[dd];
        }
        int nA = n0 + 2 * p, nB = n0 + 2 * p + 1;
        if (base + nA < N)
            *(float4*)&dstp[(base + nA) * FEAT + d0] = make_float4(lo[0], lo[1], lo[2], lo[3]);
        if (base + nB < N)
            *(float4*)&dstp[(base + nB) * FEAT + d0] = make_float4(hi[0], hi[1], hi[2], hi[3]);
        if (layer == 0) {
#pragma unroll
            for (int dd = 0; dd < 4; dd++) {
                float2 pr; pr.x = lo[dd]; pr.y = hi[dd];
                *(float2*)&hTo[(d0 + dd) * 128 + nA] = pr;
            }
        }
    }
}

// ---------------------------------------------------------------------------
// Launch sequence: 5 launches. Index 3 (ncu profiled slot) = agg1.
// ---------------------------------------------------------------------------
extern "C" void kernel_launch(void* const* d_in, const int* in_sizes, int n_in,
                              void* d_out, int out_size)
{
    const float* x  = (const float*)d_in[0];
    const int*   ei = (const int*)d_in[1];   // int32 (JAX x64 disabled)
    int N = in_sizes[0] / FEAT;
    int E = in_sizes[1] / 2;
    const int* src = ei;
    const int* dst = ei + E;

    const float* w_l0    = (const float*)d_in[2];
    const float* b_l0    = (const float*)d_in[3];
    const float* w_r0    = (const float*)d_in[4];
    const float* w_skip0 = (const float*)d_in[5];
    const float* b_skip0 = (const float*)d_in[6];
    const float* a0      = (const float*)d_in[7];
    const float* w_l1    = (const float*)d_in[8];
    const float* b_l1    = (const float*)d_in[9];
    const float* w_r1    = (const float*)d_in[10];
    const float* w_skip1 = (const float*)d_in[11];
    const float* b_skip1 = (const float*)d_in[12];
    const float* a1      = (const float*)d_in[13];
    float* out = (float*)d_out;

    size_t dsmem = (size_t)(2 * 64 * 128 + 2 * 64 * 64) * sizeof(float); // 98,304 B
    cudaFuncSetAttribute(dense_kernel, cudaFuncAttributeMaxDynamicSharedMemorySize,
                         (int)dsmem);

    int NT      = (N + DN - 1) / DN;                   // 782
    int nb      = (N + SCAN_CHUNK - 1) / SCAN_CHUNK;   // 49
    int ablocks = (N + 7) / 8;                         // 12500

    scanfill_kernel<<<nb + NT + 6, 256>>>(src, dst, N, E, nb, NT, x,       // 0
                                          w_l0, w_r0, w_skip0,
                                          w_l1, w_r1, w_skip1);

    agg_kernel<<<ablocks, 256>>>(x, N, 0);                                 // 1
    dense_kernel<<<NT, 256, dsmem>>>(x, b_l0, b_skip0, a0, out, N, 0);     // 2

    agg_kernel<<<ablocks, 256>>>(x, N, 1);                                 // 3 <- profiled
    dense_kernel<<<NT, 256, dsmem>>>(x, b_l1, b_skip1, a1, out, N, 1);     // 4
}

// round 16
// speedup vs baseline: 1.0223x; 1.0223x over previous
#include <cuda_runtime.h>
#include <cuda_bf16.h>

// Problem constants
#define MAXN 100000
#define MAXE 1600000
#define MAXNT 784          // max node tiles of 128
#define FEAT 64
#define DN 128             // nodes per dense block / tile
#define SCAN_CHUNK 2048
#define MAXBLK 64

typedef unsigned long long ull;

// Scratch (__device__ globals; allocation-free rule). Referenced ONLY from
// device code — never passed as kernel args from host.
__device__ __align__(16) float g_xT  [MAXNT * 64 * 128];  // x transposed tiles (fp32)
__device__ __align__(16) float g_h1T [MAXNT * 64 * 128];  // h1 transposed tiles (fp32)
__device__ __align__(16) float g_aggT[MAXNT * 64 * 128];  // agg transposed tiles (fp32)
__device__ __align__(16) float g_wT  [6 * 64 * 64];       // weights [k][d]
__device__ __align__(16) __nv_bfloat162 g_xb [MAXN * 32]; // bf16 gather table: x
__device__ __align__(16) __nv_bfloat162 g_h1b[MAXN * 32]; // bf16 gather table: h1
__device__ int g_cnt[MAXN];
__device__ int g_off[MAXN + 1];
__device__ int g_cur[MAXN];
__device__ int g_csr_src[MAXE];
__device__ int g_bsum[MAXBLK];
__device__ int g_bar;

// ---- packed f32x2 helpers (Blackwell PTX) ----------------------------------
__device__ __forceinline__ void fma2(ull& acc, ull av, ull wv)
{
    asm("fma.rn.f32x2 %0, %1, %2, %0;" : "+l"(acc) : "l"(av), "l"(wv));
}
__device__ __forceinline__ ull dup2(float w)
{
    ull r; asm("mov.b64 %0, {%1, %1};" : "=l"(r) : "f"(w)); return r;
}
__device__ __forceinline__ void unpk(float& lo, float& hi, ull v)
{
    asm("mov.b64 {%0, %1}, %2;" : "=f"(lo), "=f"(hi) : "l"(v));
}
__device__ __forceinline__ ull pk2(float lo, float hi)
{
    ull r; asm("mov.b64 %0, {%1, %2};" : "=l"(r) : "f"(lo), "f"(hi)); return r;
}

// ---- cp.async helpers -------------------------------------------------------
__device__ __forceinline__ void cp16(void* dst_smem, const void* src_gmem)
{
    unsigned u = (unsigned)__cvta_generic_to_shared(dst_smem);
    asm volatile("cp.async.cg.shared.global [%0], [%1], 16;"
                 :: "r"(u), "l"(src_gmem) : "memory");
}
#define CP_COMMIT() asm volatile("cp.async.commit_group;" ::: "memory")
#define CP_WAIT(n)  asm volatile("cp.async.wait_group %0;" :: "n"(n) : "memory")

// ---------------------------------------------------------------------------
// Edge histogram: full grid, one edge per thread (max MLP — proven; do NOT
// fuse into the barrier blocks, R15 regression).
// ---------------------------------------------------------------------------
__global__ void hist_kernel(const int* __restrict__ dst, int E)
{
    int e = blockIdx.x * blockDim.x + threadIdx.x;
    if (e < E) atomicAdd(&g_cnt[dst[e]], 1);
}

// Software grid barrier over the first nb blocks (co-resident).
__device__ __forceinline__ void grid_bar(int target)
{
    __syncthreads();
    if (threadIdx.x == 0) {
        __threadfence();
        atomicAdd(&g_bar, 1);
        while (atomicAdd(&g_bar, 0) < target) { }
    }
    __syncthreads();
}

// ---------------------------------------------------------------------------
// Scan + fill + transposes (R14-proven): blocks [0,nb) do the CSR scan/fill
// (zeroes g_cnt -> invariant restore; block 0 resets g_bar). Extra blocks
// [nb,nb+NT): x tile transpose -> g_xT, plus bf16 emit -> g_xb.
// [nb+NT,nb+NT+6): weight transposes -> g_wT.
// ---------------------------------------------------------------------------
__global__ void scanfill_kernel(const int* __restrict__ src,
                                const int* __restrict__ dst,
                                int N, int E, int nb, int NT,
                                const float* __restrict__ x,
                                const float* __restrict__ w0, const float* __restrict__ w1,
                                const float* __restrict__ w2, const float* __restrict__ w3,
                                const float* __restrict__ w4, const float* __restrict__ w5)
{
    __shared__ int s_sum[256];
    int t = threadIdx.x;
    int b = blockIdx.x;

    if (b >= nb) {
        int tt = b - nb;
        if (tt < NT) {
            // x tile transpose + bf16 table emit
            float* dstT = g_xT + (size_t)tt * 8192;
            for (int i = t; i < 2048; i += 256) {
                int n = i & 127, kq = i >> 7;
                int gn = tt * DN + n;
                float4 v = make_float4(0.f, 0.f, 0.f, 0.f);
                if (gn < N) v = *(const float4*)&x[gn * FEAT + kq * 4];
                dstT[(4 * kq + 0) * 128 + n] = v.x;
                dstT[(4 * kq + 1) * 128 + n] = v.y;
                dstT[(4 * kq + 2) * 128 + n] = v.z;
                dstT[(4 * kq + 3) * 128 + n] = v.w;
                if (gn < N) {
                    __nv_bfloat162 b0 = __floats2bfloat162_rn(v.x, v.y);
                    __nv_bfloat162 b1 = __floats2bfloat162_rn(v.z, v.w);
                    g_xb[gn * 32 + kq * 2]     = b0;
                    g_xb[gn * 32 + kq * 2 + 1] = b1;
                }
            }
        } else {
            int m = tt - NT;      // weight transpose 0..5
            if (m < 6) {
                const float* w = (m == 0) ? w0 : (m == 1) ? w1 : (m == 2) ? w2
                               : (m == 3) ? w3 : (m == 4) ? w4 : w5;
                for (int i = t; i < 4096; i += 256) {
                    int k = i >> 6, d = i & 63;
                    g_wT[m * 4096 + k * 64 + d] = w[d * 64 + k];
                }
            }
        }
        return;
    }

    int base = b * SCAN_CHUNK + t * 8;
    int v[8], tot = 0;
#pragma unroll
    for (int j = 0; j < 8; j++) {
        int idx = base + j;
        if (idx < N) { v[j] = g_cnt[idx]; g_cnt[idx] = 0; }
        else v[j] = 0;
        tot += v[j];
    }
    s_sum[t] = tot;
    __syncthreads();
    for (int off = 1; off < 256; off <<= 1) {
        int xv = (t >= off) ? s_sum[t - off] : 0;
        __syncthreads();
        s_sum[t] += xv;
        __syncthreads();
    }
    if (t == 255) g_bsum[b] = s_sum[255];
    int run = s_sum[t] - tot;

    grid_bar(nb);

    int bpre = 0;
    for (int bb = 0; bb < b; bb++) bpre += g_bsum[bb];
    run += bpre;
#pragma unroll
    for (int j = 0; j < 8; j++) {
        int idx = base + j;
        if (idx < N) { g_off[idx] = run; g_cur[idx] = run; }
        run += v[j];
    }
    if (b == nb - 1 && t == 255) g_off[N] = E;

    grid_bar(2 * nb);

    int tg = b * blockDim.x + t;
    int T  = nb * blockDim.x;
    for (int eb = tg * 8; eb < E; eb += T * 8) {
#pragma unroll
        for (int j = 0; j < 8; j++) {
            int e = eb + j;
            if (e < E) {
                int p = atomicAdd(&g_cur[dst[e]], 1);
                g_csr_src[p] = src[e];
            }
        }
    }
    if (b == 0 && t == 0) g_bar = 0;   // restore invariant
}

// ---------------------------------------------------------------------------
// Aggregate: 8 warps/block = 8 nodes; gather source is the bf16 table (half
// the L2 traffic of fp32); lane covers feats (2l, 2l+1) as one bf16x2 load.
// fp32 accumulate. Writes mean TRANSPOSED (fp32) into g_aggT tiles via a
// small bank-safe smem bounce.
// ---------------------------------------------------------------------------
__global__ void agg_kernel(int N, int layer)
{
    __shared__ float s[64 * 9];
    int b = blockIdx.x;
    int warp = threadIdx.x >> 5;
    int lane = threadIdx.x & 31;
    int node = b * 8 + warp;
    const __nv_bfloat162* hb = layer ? g_h1b : g_xb;

    float ax = 0.f, ay = 0.f;
    int deg = 0;
    if (node < N) {
        int start = g_off[node];
        deg = g_off[node + 1] - start;
        int i = 0;
        for (; i + 8 <= deg; i += 8) {
            int sidx[8];
#pragma unroll
            for (int j = 0; j < 8; j++) sidx[j] = g_csr_src[start + i + j];
            __nv_bfloat162 v[8];
#pragma unroll
            for (int j = 0; j < 8; j++) v[j] = hb[sidx[j] * 32 + lane];
#pragma unroll
            for (int j = 0; j < 8; j++) {
                float2 f = __bfloat1622float2(v[j]);
                ax += f.x; ay += f.y;
            }
        }
        for (; i < deg; i++) {
            int sidx = g_csr_src[start + i];
            float2 f = __bfloat1622float2(hb[sidx * 32 + lane]);
            ax += f.x; ay += f.y;
        }
    }
    float inv = 1.f / fmaxf((float)deg, 1.f);
    s[(2 * lane) * 9 + warp]     = ax * inv;
    s[(2 * lane + 1) * 9 + warp] = ay * inv;
    __syncthreads();

    int nbase = b * 8;
    int tile  = nbase >> 7;
    int nb2   = nbase & 127;
    float* dst = g_aggT + (size_t)tile * 8192;
    for (int i = threadIdx.x; i < 512; i += 256) {
        int k = i >> 3, n = i & 7;
        dst[k * 128 + nb2 + n] = s[k * 9 + n];
    }
}

// ---------------------------------------------------------------------------
// Dense phase (proven 57.8us core): pre-transposed inputs -> pure cp.async
// staging, double-buffered (96KB, 2 blocks/SM). Thread tile 4d x 8n, f32x2
// k-loop. Phases: agg@wl -> h@wr -> +bl,PReLU (regs) -> x@ws -> +bs.
// Layer 0 epilogue writes h1T (fp32 tiles, for dense1) + g_h1b (bf16 natural,
// for agg1). Layer 1 writes out (fp32 natural).
// ---------------------------------------------------------------------------
__device__ __forceinline__ void dense_compute(const float* __restrict__ act,
                                              const float* __restrict__ w,
                                              ull acc[4][4], int d0, int n0)
{
#pragma unroll 4
    for (int k = 0; k < 64; k++) {
        float4 w4 = *(const float4*)&w[k * 64 + d0];
        ull wd[4];
        wd[0] = dup2(w4.x); wd[1] = dup2(w4.y);
        wd[2] = dup2(w4.z); wd[3] = dup2(w4.w);
        longlong2 p01 = *(const longlong2*)&act[k * 128 + n0];
        longlong2 p23 = *(const longlong2*)&act[k * 128 + n0 + 4];
        ull av[4];
        av[0] = (ull)p01.x; av[1] = (ull)p01.y;
        av[2] = (ull)p23.x; av[3] = (ull)p23.y;
#pragma unroll
        for (int dd = 0; dd < 4; dd++)
#pragma unroll
            for (int p = 0; p < 4; p++)
                fma2(acc[dd][p], av[p], wd[dd]);
    }
}

__global__ void __launch_bounds__(256, 2) dense_kernel(
    const float* __restrict__ b_l, const float* __restrict__ b_skip,
    const float* __restrict__ a,
    float* __restrict__ out, int N, int layer)
{
    extern __shared__ __align__(16) float sm[];
    float* actA = sm;                  // [64][128]
    float* actB = sm + 8192;
    float* wA   = sm + 16384;          // [64][64]
    float* wB   = sm + 16384 + 4096;

    int tid  = threadIdx.x;
    int base = blockIdx.x * DN;
    int d0   = (tid & 15) * 4;
    int n0   = (tid >> 4) * 8;

    const float* aT = g_aggT + (size_t)blockIdx.x * 8192;
    const float* xT = g_xT   + (size_t)blockIdx.x * 8192;
    const float* hT = layer ? (g_h1T + (size_t)blockIdx.x * 8192) : xT;
    const float* wb = g_wT + layer * 3 * 4096;

    // prologue: stage p0 and p1
    for (int i = tid; i < 2048; i += 256) cp16(&actA[i * 4], &aT[i * 4]);
    for (int i = tid; i < 1024; i += 256) cp16(&wA[i * 4], &wb[i * 4]);
    CP_COMMIT();                                            // g1
    for (int i = tid; i < 2048; i += 256) cp16(&actB[i * 4], &hT[i * 4]);
    for (int i = tid; i < 1024; i += 256) cp16(&wB[i * 4], &wb[4096 + i * 4]);
    CP_COMMIT();                                            // g2

    float bl[4], bs[4], apar[4];
#pragma unroll
    for (int dd = 0; dd < 4; dd++) {
        bl[dd]   = b_l[d0 + dd];
        bs[dd]   = b_skip[d0 + dd];
        apar[dd] = a[d0 + dd];
    }

    ull acc[4][4];
#pragma unroll
    for (int dd = 0; dd < 4; dd++)
#pragma unroll
        for (int p = 0; p < 4; p++) acc[dd][p] = 0ULL;

    // ---- phase 0: agg @ wl ----
    CP_WAIT(1);
    __syncthreads();
    dense_compute(actA, wA, acc, d0, n0);
    __syncthreads();     // all reads of actA/wA done before g3 overwrites

    // stage p2 (layer0 reuses actB = x; layer1 restages actA with xT)
    if (layer) {
        for (int i = tid; i < 2048; i += 256) cp16(&actA[i * 4], &xT[i * 4]);
    }
    for (int i = tid; i < 1024; i += 256) cp16(&wA[i * 4], &wb[8192 + i * 4]);
    CP_COMMIT();                                            // g3

    // ---- phase 1: h @ wr ----
    CP_WAIT(1);
    __syncthreads();
    dense_compute(actB, wB, acc, d0, n0);

    // mid-epilogue in registers: acc = PReLU(acc + bl)
#pragma unroll
    for (int dd = 0; dd < 4; dd++)
#pragma unroll
        for (int p = 0; p < 4; p++) {
            float lo, hi;
            unpk(lo, hi, acc[dd][p]);
            lo += bl[dd]; hi += bl[dd];
            lo = (lo >= 0.f) ? lo : apar[dd] * lo;
            hi = (hi >= 0.f) ? hi : apar[dd] * hi;
            acc[dd][p] = pk2(lo, hi);
        }

    // ---- phase 2: x @ ws ----
    CP_WAIT(0);
    __syncthreads();
    dense_compute(layer ? actA : actB, wA, acc, d0, n0);

    // epilogue
    float* hTo = g_h1T + (size_t)blockIdx.x * 8192;
#pragma unroll
    for (int p = 0; p < 4; p++) {
        float lo[4], hi[4];
#pragma unroll
        for (int dd = 0; dd < 4; dd++) {
            unpk(lo[dd], hi[dd], acc[dd][p]);
            lo[dd] += bs[dd]; hi[dd] += bs[dd];
        }
        int nA = n0 + 2 * p, nB = n0 + 2 * p + 1;
        if (layer) {
            // fp32 natural output
            if (base + nA < N)
                *(float4*)&out[(base + nA) * FEAT + d0] = make_float4(lo[0], lo[1], lo[2], lo[3]);
            if (base + nB < N)
                *(float4*)&out[(base + nB) * FEAT + d0] = make_float4(hi[0], hi[1], hi[2], hi[3]);
        } else {
            // h1T fp32 tiles (for dense1 staging)
#pragma unroll
            for (int dd = 0; dd < 4; dd++) {
                float2 pr; pr.x = lo[dd]; pr.y = hi[dd];
                *(float2*)&hTo[(d0 + dd) * 128 + nA] = pr;
            }
            // bf16 natural table (for agg1 gather)
            if (base + nA < N) {
                __nv_bfloat162 b0 = __floats2bfloat162_rn(lo[0], lo[1]);
                __nv_bfloat162 b1 = __floats2bfloat162_rn(lo[2], lo[3]);
                *(uint2*)&g_h1b[(base + nA) * 32 + (d0 >> 1)] =
                    make_uint2(*(unsigned*)&b0, *(unsigned*)&b1);
            }
            if (base + nB < N) {
                __nv_bfloat162 b0 = __floats2bfloat162_rn(hi[0], hi[1]);
                __nv_bfloat162 b1 = __floats2bfloat162_rn(hi[2], hi[3]);
                *(uint2*)&g_h1b[(base + nB) * 32 + (d0 >> 1)] =
                    make_uint2(*(unsigned*)&b0, *(unsigned*)&b1);
            }
        }
    }
}

// ---------------------------------------------------------------------------
// Launch sequence: 6 launches. Index 3 (ncu profiled slot) = dense0.
// ---------------------------------------------------------------------------
extern "C" void kernel_launch(void* const* d_in, const int* in_sizes, int n_in,
                              void* d_out, int out_size)
{
    const float* x  = (const float*)d_in[0];
    const int*   ei = (const int*)d_in[1];   // int32 (JAX x64 disabled)
    int N = in_sizes[0] / FEAT;
    int E = in_sizes[1] / 2;
    const int* src = ei;
    const int* dst = ei + E;

    const float* w_l0    = (const float*)d_in[2];
    const float* b_l0    = (const float*)d_in[3];
    const float* w_r0    = (const float*)d_in[4];
    const float* w_skip0 = (const float*)d_in[5];
    const float* b_skip0 = (const float*)d_in[6];
    const float* a0      = (const float*)d_in[7];
    const float* w_l1    = (const float*)d_in[8];
    const float* b_l1    = (const float*)d_in[9];
    const float* w_r1    = (const float*)d_in[10];
    const float* w_skip1 = (const float*)d_in[11];
    const float* b_skip1 = (const float*)d_in[12];
    const float* a1      = (const float*)d_in[13];
    float* out = (float*)d_out;

    size_t dsmem = (size_t)(2 * 64 * 128 + 2 * 64 * 64) * sizeof(float); // 98,304 B
    cudaFuncSetAttribute(dense_kernel, cudaFuncAttributeMaxDynamicSharedMemorySize,
                         (int)dsmem);

    int eblocks = (E + 255) / 256;
    int NT      = (N + DN - 1) / DN;                   // 782
    int nb      = (N + SCAN_CHUNK - 1) / SCAN_CHUNK;   // 49
    int ablocks = (N + 7) / 8;                         // 12500

    hist_kernel<<<eblocks, 256>>>(dst, E);                                 // 0
    scanfill_kernel<<<nb + NT + 6, 256>>>(src, dst, N, E, nb, NT, x,       // 1
                                          w_l0, w_r0, w_skip0,
                                          w_l1, w_r1, w_skip1);

    agg_kernel<<<ablocks, 256>>>(N, 0);                                    // 2
    dense_kernel<<<NT, 256, dsmem>>>(b_l0, b_skip0, a0, out, N, 0);        // 3 <- profiled

    agg_kernel<<<ablocks, 256>>>(N, 1);                                    // 4
    dense_kernel<<<NT, 256, dsmem>>>(b_l1, b_skip1, a1, out, N, 1);        // 5
}

// round 17
// speedup vs baseline: 1.2195x; 1.1928x over previous
#include <cuda_runtime.h>

// Problem constants
#define MAXN 100000
#define MAXE 1600000
#define MAXNT 784          // max node tiles of 128
#define FEAT 64
#define DN 128             // nodes per dense block / tile
#define SCAN_CHUNK 2048
#define MAXBLK 64

typedef unsigned long long ull;

// Scratch (__device__ globals; allocation-free rule). Referenced ONLY from
// device code — never passed as kernel args from host.
__device__ __align__(16) float g_h1  [MAXN * FEAT];       // layer-0 out, [n][k]
__device__ __align__(16) float g_xT  [MAXNT * 64 * 128];  // x transposed tiles
__device__ __align__(16) float g_h1T [MAXNT * 64 * 128];  // h1 transposed tiles
__device__ __align__(16) float g_aggT[MAXNT * 64 * 128];  // agg transposed tiles
__device__ __align__(16) float g_wT  [6 * 64 * 64];       // weights [k][d]
__device__ int g_cnt[MAXN];
__device__ int g_off[MAXN + 1];
__device__ int g_cur[MAXN];
__device__ int g_csr_src[MAXE];
__device__ int g_bsum[MAXBLK];
__device__ int g_bar;

// ---- packed f32x2 helpers (Blackwell PTX) ----------------------------------
__device__ __forceinline__ void fma2(ull& acc, ull av, ull wv)
{
    asm("fma.rn.f32x2 %0, %1, %2, %0;" : "+l"(acc) : "l"(av), "l"(wv));
}
__device__ __forceinline__ ull dup2(float w)
{
    ull r; asm("mov.b64 %0, {%1, %1};" : "=l"(r) : "f"(w)); return r;
}
__device__ __forceinline__ void unpk(float& lo, float& hi, ull v)
{
    asm("mov.b64 {%0, %1}, %2;" : "=f"(lo), "=f"(hi) : "l"(v));
}
__device__ __forceinline__ ull pk2(float lo, float hi)
{
    ull r; asm("mov.b64 %0, {%1, %2};" : "=l"(r) : "f"(lo), "f"(hi)); return r;
}

// ---- cp.async helpers -------------------------------------------------------
__device__ __forceinline__ void cp16(void* dst_smem, const void* src_gmem)
{
    unsigned u = (unsigned)__cvta_generic_to_shared(dst_smem);
    asm volatile("cp.async.cg.shared.global [%0], [%1], 16;"
                 :: "r"(u), "l"(src_gmem) : "memory");
}
#define CP_COMMIT() asm volatile("cp.async.commit_group;" ::: "memory")
#define CP_WAIT(n)  asm volatile("cp.async.wait_group %0;" :: "n"(n) : "memory")

// ---------------------------------------------------------------------------
// Launch 0: full-grid edge histogram + transpose riders.
// Blocks [0,eblocks): one edge per thread (max MLP for REDs).
// Blocks [eblocks, eblocks+NT): x tile transpose -> g_xT (smem-free).
// Blocks [eblocks+NT, +6): weight transposes -> g_wT.
// ---------------------------------------------------------------------------
__global__ void hist_kernel(const int* __restrict__ dst, int E, int eblocks,
                            const float* __restrict__ x, int N, int NT,
                            const float* __restrict__ w0, const float* __restrict__ w1,
                            const float* __restrict__ w2, const float* __restrict__ w3,
                            const float* __restrict__ w4, const float* __restrict__ w5)
{
    int b = blockIdx.x;
    int t = threadIdx.x;

    if (b < eblocks) {
        int e = b * blockDim.x + t;
        if (e < E) atomicAdd(&g_cnt[dst[e]], 1);
        return;
    }
    int tt = b - eblocks;
    if (tt < NT) {
        float* dstT = g_xT + (size_t)tt * 8192;
        for (int i = t; i < 2048; i += 256) {
            int n = i & 127, kq = i >> 7;
            int gn = tt * DN + n;
            float4 v = make_float4(0.f, 0.f, 0.f, 0.f);
            if (gn < N) v = *(const float4*)&x[gn * FEAT + kq * 4];
            dstT[(4 * kq + 0) * 128 + n] = v.x;
            dstT[(4 * kq + 1) * 128 + n] = v.y;
            dstT[(4 * kq + 2) * 128 + n] = v.z;
            dstT[(4 * kq + 3) * 128 + n] = v.w;
        }
    } else {
        int m = tt - NT;      // weight transpose 0..5
        if (m < 6) {
            const float* w = (m == 0) ? w0 : (m == 1) ? w1 : (m == 2) ? w2
                           : (m == 3) ? w3 : (m == 4) ? w4 : w5;
            for (int i = t; i < 4096; i += 256) {
                int k = i >> 6, d = i & 63;
                g_wT[m * 4096 + k * 64 + d] = w[d * 64 + k];
            }
        }
    }
}

// Software grid barrier over nb co-resident blocks.
__device__ __forceinline__ void grid_bar(int target)
{
    __syncthreads();
    if (threadIdx.x == 0) {
        __threadfence();
        atomicAdd(&g_bar, 1);
        while (atomicAdd(&g_bar, 0) < target) { }
    }
    __syncthreads();
}

// ---------------------------------------------------------------------------
// Launch 1: scan-only (49 blocks). Local exclusive scan (zeroes g_cnt ->
// restores call-entry invariant) -> bar -> global offsets (+g_off[N]=E).
// g_bar is NOT reset here (a spinning block could deadlock); fill resets it.
// ---------------------------------------------------------------------------
__global__ void scan_kernel(int N, int E, int nb)
{
    __shared__ int s_sum[256];
    int t = threadIdx.x;
    int b = blockIdx.x;

    int base = b * SCAN_CHUNK + t * 8;
    int v[8], tot = 0;
#pragma unroll
    for (int j = 0; j < 8; j++) {
        int idx = base + j;
        if (idx < N) { v[j] = g_cnt[idx]; g_cnt[idx] = 0; }
        else v[j] = 0;
        tot += v[j];
    }
    s_sum[t] = tot;
    __syncthreads();
    for (int off = 1; off < 256; off <<= 1) {
        int xv = (t >= off) ? s_sum[t - off] : 0;
        __syncthreads();
        s_sum[t] += xv;
        __syncthreads();
    }
    if (t == 255) g_bsum[b] = s_sum[255];
    int run = s_sum[t] - tot;

    grid_bar(nb);

    int bpre = 0;
    for (int bb = 0; bb < b; bb++) bpre += g_bsum[bb];
    run += bpre;
#pragma unroll
    for (int j = 0; j < 8; j++) {
        int idx = base + j;
        if (idx < N) { g_off[idx] = run; g_cur[idx] = run; }
        run += v[j];
    }
    if (b == nb - 1 && t == 255) g_off[N] = E;
}

// ---------------------------------------------------------------------------
// Launch 2: fill (full grid, 1 edge/thread — edge phases want max MLP).
// Also resets g_bar (scan is fully retired at this kernel's start).
// ---------------------------------------------------------------------------
__global__ void fill_kernel(const int* __restrict__ src,
                            const int* __restrict__ dst, int E)
{
    int e = blockIdx.x * blockDim.x + threadIdx.x;
    if (e < E) {
        int p = atomicAdd(&g_cur[dst[e]], 1);
        g_csr_src[p] = src[e];
    }
    if (blockIdx.x == 0 && threadIdx.x == 0) g_bar = 0;   // restore invariant
}

// ---------------------------------------------------------------------------
// Aggregate (R14-proven): 8 warps/block = 8 nodes; lane covers feats (2l,2l+1)
// as float2. fp32 gather (bf16 gave no win: transaction-bound, not byte-bound).
// Writes mean TRANSPOSED into g_aggT tiles via a bank-safe smem bounce.
// ---------------------------------------------------------------------------
__global__ void agg_kernel(const float* __restrict__ x, int N, int layer)
{
    __shared__ float s[64 * 9];
    int b = blockIdx.x;
    int warp = threadIdx.x >> 5;
    int lane = threadIdx.x & 31;
    int node = b * 8 + warp;
    const float2* h2 = (const float2*)(layer ? g_h1 : x);

    float ax = 0.f, ay = 0.f;
    int deg = 0;
    if (node < N) {
        int start = g_off[node];
        deg = g_off[node + 1] - start;
        int i = 0;
        for (; i + 8 <= deg; i += 8) {
            int sidx[8];
#pragma unroll
            for (int j = 0; j < 8; j++) sidx[j] = g_csr_src[start + i + j];
            float2 v[8];
#pragma unroll
            for (int j = 0; j < 8; j++) v[j] = h2[sidx[j] * 32 + lane];
            ax += ((v[0].x + v[1].x) + (v[2].x + v[3].x))
                + ((v[4].x + v[5].x) + (v[6].x + v[7].x));
            ay += ((v[0].y + v[1].y) + (v[2].y + v[3].y))
                + ((v[4].y + v[5].y) + (v[6].y + v[7].y));
        }
        for (; i < deg; i++) {
            int sidx = g_csr_src[start + i];
            float2 v = h2[sidx * 32 + lane];
            ax += v.x; ay += v.y;
        }
    }
    float inv = 1.f / fmaxf((float)deg, 1.f);
    s[(2 * lane) * 9 + warp]     = ax * inv;
    s[(2 * lane + 1) * 9 + warp] = ay * inv;
    __syncthreads();

    int nbase = b * 8;
    int tile  = nbase >> 7;
    int nb2   = nbase & 127;
    float* dst = g_aggT + (size_t)tile * 8192;
    for (int i = threadIdx.x; i < 512; i += 256) {
        int k = i >> 3, n = i & 7;
        dst[k * 128 + nb2 + n] = s[k * 9 + n];
    }
}

// ---------------------------------------------------------------------------
// Dense phase (R14-proven, 57.8us): pre-transposed inputs -> pure cp.async
// staging, double-buffered (96KB, 2 blocks/SM). Thread tile 4d x 8n, f32x2
// k-loop. Phases: agg@wl -> h@wr -> +bl,PReLU (regs) -> x@ws -> +bs.
// Layer 0 epilogue dual-writes h1 natural (for agg1 gather) + h1T tiles
// (for dense1 staging).
// ---------------------------------------------------------------------------
__device__ __forceinline__ void dense_compute(const float* __restrict__ act,
                                              const float* __restrict__ w,
                                              ull acc[4][4], int d0, int n0)
{
#pragma unroll 4
    for (int k = 0; k < 64; k++) {
        float4 w4 = *(const float4*)&w[k * 64 + d0];
        ull wd[4];
        wd[0] = dup2(w4.x); wd[1] = dup2(w4.y);
        wd[2] = dup2(w4.z); wd[3] = dup2(w4.w);
        longlong2 p01 = *(const longlong2*)&act[k * 128 + n0];
        longlong2 p23 = *(const longlong2*)&act[k * 128 + n0 + 4];
        ull av[4];
        av[0] = (ull)p01.x; av[1] = (ull)p01.y;
        av[2] = (ull)p23.x; av[3] = (ull)p23.y;
#pragma unroll
        for (int dd = 0; dd < 4; dd++)
#pragma unroll
            for (int p = 0; p < 4; p++)
                fma2(acc[dd][p], av[p], wd[dd]);
    }
}

__global__ void __launch_bounds__(256, 2) dense_kernel(
    const float* __restrict__ b_l, const float* __restrict__ b_skip,
    const float* __restrict__ a,
    float* __restrict__ out, int N, int layer)
{
    extern __shared__ __align__(16) float sm[];
    float* actA = sm;                  // [64][128]
    float* actB = sm + 8192;
    float* wA   = sm + 16384;          // [64][64]
    float* wB   = sm + 16384 + 4096;

    int tid  = threadIdx.x;
    int base = blockIdx.x * DN;
    int d0   = (tid & 15) * 4;
    int n0   = (tid >> 4) * 8;

    const float* aT = g_aggT + (size_t)blockIdx.x * 8192;
    const float* xT = g_xT   + (size_t)blockIdx.x * 8192;
    const float* hT = layer ? (g_h1T + (size_t)blockIdx.x * 8192) : xT;
    const float* wb = g_wT + layer * 3 * 4096;

    // prologue: stage p0 and p1
    for (int i = tid; i < 2048; i += 256) cp16(&actA[i * 4], &aT[i * 4]);
    for (int i = tid; i < 1024; i += 256) cp16(&wA[i * 4], &wb[i * 4]);
    CP_COMMIT();                                            // g1
    for (int i = tid; i < 2048; i += 256) cp16(&actB[i * 4], &hT[i * 4]);
    for (int i = tid; i < 1024; i += 256) cp16(&wB[i * 4], &wb[4096 + i * 4]);
    CP_COMMIT();                                            // g2

    float bl[4], bs[4], apar[4];
#pragma unroll
    for (int dd = 0; dd < 4; dd++) {
        bl[dd]   = b_l[d0 + dd];
        bs[dd]   = b_skip[d0 + dd];
        apar[dd] = a[d0 + dd];
    }

    ull acc[4][4];
#pragma unroll
    for (int dd = 0; dd < 4; dd++)
#pragma unroll
        for (int p = 0; p < 4; p++) acc[dd][p] = 0ULL;

    // ---- phase 0: agg @ wl ----
    CP_WAIT(1);
    __syncthreads();
    dense_compute(actA, wA, acc, d0, n0);
    __syncthreads();     // all reads of actA/wA done before g3 overwrites

    // stage p2 (layer0 reuses actB = x; layer1 restages actA with xT)
    if (layer) {
        for (int i = tid; i < 2048; i += 256) cp16(&actA[i * 4], &xT[i * 4]);
    }
    for (int i = tid; i < 1024; i += 256) cp16(&wA[i * 4], &wb[8192 + i * 4]);
    CP_COMMIT();                                            // g3

    // ---- phase 1: h @ wr ----
    CP_WAIT(1);
    __syncthreads();
    dense_compute(actB, wB, acc, d0, n0);

    // mid-epilogue in registers: acc = PReLU(acc + bl)
#pragma unroll
    for (int dd = 0; dd < 4; dd++)
#pragma unroll
        for (int p = 0; p < 4; p++) {
            float lo, hi;
            unpk(lo, hi, acc[dd][p]);
            lo += bl[dd]; hi += bl[dd];
            lo = (lo >= 0.f) ? lo : apar[dd] * lo;
            hi = (hi >= 0.f) ? hi : apar[dd] * hi;
            acc[dd][p] = pk2(lo, hi);
        }

    // ---- phase 2: x @ ws ----
    CP_WAIT(0);
    __syncthreads();
    dense_compute(layer ? actA : actB, wA, acc, d0, n0);

    // epilogue: out = acc + bs; layer0 also writes h1T tiles
    float* dstp = layer ? out : g_h1;
    float* hTo  = g_h1T + (size_t)blockIdx.x * 8192;
#pragma unroll
    for (int p = 0; p < 4; p++) {
        float lo[4], hi[4];
#pragma unroll
        for (int dd = 0; dd < 4; dd++) {
            unpk(lo[dd], hi[dd], acc[dd][p]);
            lo[dd] += bs[dd]; hi[dd] += bs[dd];
        }
        int nA = n0 + 2 * p, nB = n0 + 2 * p + 1;
        if (base + nA < N)
            *(float4*)&dstp[(base + nA) * FEAT + d0] = make_float4(lo[0], lo[1], lo[2], lo[3]);
        if (base + nB < N)
            *(float4*)&dstp[(base + nB) * FEAT + d0] = make_float4(hi[0], hi[1], hi[2], hi[3]);
        if (layer == 0) {
#pragma unroll
            for (int dd = 0; dd < 4; dd++) {
                float2 pr; pr.x = lo[dd]; pr.y = hi[dd];
                *(float2*)&hTo[(d0 + dd) * 128 + nA] = pr;
            }
        }
    }
}

// ---------------------------------------------------------------------------
// Launch sequence: 7 launches, all edge phases full-grid.
// Index 3 (ncu profiled slot) = agg0.
// ---------------------------------------------------------------------------
extern "C" void kernel_launch(void* const* d_in, const int* in_sizes, int n_in,
                              void* d_out, int out_size)
{
    const float* x  = (const float*)d_in[0];
    const int*   ei = (const int*)d_in[1];   // int32 (JAX x64 disabled)
    int N = in_sizes[0] / FEAT;
    int E = in_sizes[1] / 2;
    const int* src = ei;
    const int* dst = ei + E;

    const float* w_l0    = (const float*)d_in[2];
    const float* b_l0    = (const float*)d_in[3];
    const float* w_r0    = (const float*)d_in[4];
    const float* w_skip0 = (const float*)d_in[5];
    const float* b_skip0 = (const float*)d_in[6];
    const float* a0      = (const float*)d_in[7];
    const float* w_l1    = (const float*)d_in[8];
    const float* b_l1    = (const float*)d_in[9];
    const float* w_r1    = (const float*)d_in[10];
    const float* w_skip1 = (const float*)d_in[11];
    const float* b_skip1 = (const float*)d_in[12];
    const float* a1      = (const float*)d_in[13];
    float* out = (float*)d_out;

    size_t dsmem = (size_t)(2 * 64 * 128 + 2 * 64 * 64) * sizeof(float); // 98,304 B
    cudaFuncSetAttribute(dense_kernel, cudaFuncAttributeMaxDynamicSharedMemorySize,
                         (int)dsmem);

    int eblocks = (E + 255) / 256;                     // 6250
    int NT      = (N + DN - 1) / DN;                   // 782
    int nb      = (N + SCAN_CHUNK - 1) / SCAN_CHUNK;   // 49
    int ablocks = (N + 7) / 8;                         // 12500

    hist_kernel<<<eblocks + NT + 6, 256>>>(dst, E, eblocks, x, N, NT,      // 0
                                           w_l0, w_r0, w_skip0,
                                           w_l1, w_r1, w_skip1);
    scan_kernel<<<nb, 256>>>(N, E, nb);                                    // 1
    fill_kernel<<<eblocks, 256>>>(src, dst, E);                            // 2

    agg_kernel<<<ablocks, 256>>>(x, N, 0);                                 // 3 <- profiled
    dense_kernel<<<NT, 256, dsmem>>>(b_l0, b_skip0, a0, out, N, 0);        // 4

    agg_kernel<<<ablocks, 256>>>(x, N, 1);                                 // 5
    dense_kernel<<<NT, 256, dsmem>>>(b_l1, b_skip1, a1, out, N, 1);        // 6
}